// round 17
// baseline (speedup 1.0000x reference)
#include <cuda_runtime.h>
#include <cuda_bf16.h>
#include <cuda_fp16.h>
#include <math.h>
#include <stdint.h>

// ============================================================================
// MultiHeadAttention: x[2,2048,768] -> out[2,2048,768]
// R17: out-GEMM ring deepened to 4 stages (prefetch distance 3, wait_group 2,
// __launch_bounds__(256,2)) — covers the cp.async latency that kept issue at
// 22%. qkv GEMM (3-stage ring) + attention unchanged from R16 (223.3us).
// ============================================================================

#define BATCH 2
#define SEQ   2048
#define DM    768
#define NH    12
#define DKH   64
#define MTOK  (BATCH*SEQ)   // 4096

// scratch
__device__ __half g_xh[MTOK*DM], g_xl[MTOK*DM];
__device__ __half g_qf[MTOK*DM], g_kf[MTOK*DM], g_vf[MTOK*DM];
__device__ __half g_ch[MTOK*DM], g_cl[MTOK*DM];
__device__ __half g_wq[DM*DM], g_wk[DM*DM], g_wv[DM*DM], g_wo[DM*DM];

// ----------------------------------------------------------------------------
// helpers
// ----------------------------------------------------------------------------
__device__ __forceinline__ uint32_t smem_u32(const void* p) {
    uint32_t a;
    asm("{ .reg .u64 t; cvta.to.shared.u64 t, %1; cvt.u32.u64 %0, t; }"
        : "=r"(a) : "l"(p));
    return a;
}
__device__ __forceinline__ void cp16(uint32_t dst, const void* src) {
    asm volatile("cp.async.cg.shared.global [%0], [%1], 16;"
                 :: "r"(dst), "l"(src) : "memory");
}
__device__ __forceinline__ void ldsm4(uint32_t* r, uint32_t addr) {
    asm volatile("ldmatrix.sync.aligned.m8n8.x4.shared.b16 {%0,%1,%2,%3}, [%4];"
                 : "=r"(r[0]), "=r"(r[1]), "=r"(r[2]), "=r"(r[3]) : "r"(addr));
}
__device__ __forceinline__ void ldsm4t(uint32_t* r, uint32_t addr) {
    asm volatile("ldmatrix.sync.aligned.m8n8.x4.trans.shared.b16 {%0,%1,%2,%3}, [%4];"
                 : "=r"(r[0]), "=r"(r[1]), "=r"(r[2]), "=r"(r[3]) : "r"(addr));
}
__device__ __forceinline__ void mma16816h(float* c, const uint32_t* a,
                                          uint32_t b0, uint32_t b1) {
    asm("mma.sync.aligned.m16n8k16.row.col.f32.f16.f16.f32 "
        "{%0,%1,%2,%3}, {%4,%5,%6,%7}, {%8,%9}, {%0,%1,%2,%3};"
        : "+f"(c[0]), "+f"(c[1]), "+f"(c[2]), "+f"(c[3])
        : "r"(a[0]), "r"(a[1]), "r"(a[2]), "r"(a[3]), "r"(b0), "r"(b1));
}
__device__ __forceinline__ uint32_t h2ex2(uint32_t s) {
    uint32_t d; asm("ex2.approx.f16x2 %0, %1;" : "=r"(d) : "r"(s)); return d;
}
__device__ __forceinline__ uint32_t hadd2(uint32_t a, uint32_t b) {
    uint32_t d; asm("add.rn.f16x2 %0, %1, %2;" : "=r"(d) : "r"(a), "r"(b));
    return d;
}
__device__ __forceinline__ uint32_t pack_h2(float a, float b) {
    __half2 t = __floats2half2_rn(a, b);
    return *(uint32_t*)&t;
}
__device__ __forceinline__ uint32_t pack_h2lo(float a, float b, uint32_t hi) {
    __half2 h = *(__half2*)&hi;
    __half2 t = __floats2half2_rn(a - __half2float(h.x),
                                  b - __half2float(h.y));
    return *(uint32_t*)&t;
}

// ----------------------------------------------------------------------------
// merged conversion: x -> fp16 hi/lo split; 4 weights -> fp16 single
// ----------------------------------------------------------------------------
#define NX4C (MTOK*DM/4)    // 786432
#define NW4C (DM*DM/4)      // 147456

__global__ void __launch_bounds__(256) cvt_all_kernel(
    const float* __restrict__ x, __half* __restrict__ xh, __half* __restrict__ xl,
    const float* __restrict__ w0, __half* __restrict__ d0,
    const float* __restrict__ w1, __half* __restrict__ d1,
    const float* __restrict__ w2, __half* __restrict__ d2,
    const float* __restrict__ w3, __half* __restrict__ d3)
{
    int i = blockIdx.x * blockDim.x + threadIdx.x;
    if (i < NX4C) {
        float4 v = ((const float4*)x)[i];
        uint32_t h0 = pack_h2(v.x, v.y), h1 = pack_h2(v.z, v.w);
        ((uint32_t*)xh)[2*i]   = h0;
        ((uint32_t*)xh)[2*i+1] = h1;
        ((uint32_t*)xl)[2*i]   = pack_h2lo(v.x, v.y, h0);
        ((uint32_t*)xl)[2*i+1] = pack_h2lo(v.z, v.w, h1);
        return;
    }
    int j = i - NX4C;
    if (j >= 4 * NW4C) return;
    int w = j / NW4C, k = j % NW4C;
    const float* s; __half* d;
    switch (w) {
        case 0: s = w0; d = d0; break;
        case 1: s = w1; d = d1; break;
        case 2: s = w2; d = d2; break;
        default: s = w3; d = d3; break;
    }
    float4 v = ((const float4*)s)[k];
    ((uint32_t*)d)[2*k]   = pack_h2(v.x, v.y);
    ((uint32_t*)d)[2*k+1] = pack_h2(v.z, v.w);
}

// ----------------------------------------------------------------------------
// fp16 2-split qkv GEMM 128x128, 3-stage ring (unchanged from R16).
// ----------------------------------------------------------------------------
#define MM_ROWB   80
#define MM_ARR    10240
#define MM_STAGE  (3*MM_ARR)             // Ah|Al|B = 30720
#define MM_SMEM   (3*MM_STAGE)           // 92160

__device__ __forceinline__ void mm_load_chunk(
    const __half* __restrict__ Ah, const __half* __restrict__ Al,
    const __half* __restrict__ B,
    int m0, int n0, int k0, uint32_t stage, int tid)
{
    const __half* srcs[3] = {Ah, Al, B};
    const int r0s[3] = {m0, m0, n0};
#pragma unroll
    for (int a = 0; a < 3; a++) {
#pragma unroll
        for (int i = 0; i < 2; i++) {
            int f = tid + i * 256;
            int r = f >> 2;
            int c8 = (f & 3) * 8;
            cp16(stage + a * MM_ARR + r * MM_ROWB + c8 * 2,
                 srcs[a] + (size_t)(r0s[a] + r) * DM + k0 + c8);
        }
    }
    asm volatile("cp.async.commit_group;" ::: "memory");
}

__global__ void __launch_bounds__(256) tc_qkv_kernel(
    const __half* __restrict__ Xh, const __half* __restrict__ Xl,
    const __half* __restrict__ Wq, const float* __restrict__ bq,
    __half* __restrict__ Qf,
    const __half* __restrict__ Wk, const float* __restrict__ bk,
    __half* __restrict__ Kf,
    const __half* __restrict__ Wv, const float* __restrict__ bv,
    __half* __restrict__ Vf)
{
    extern __shared__ char smem[];
    const __half* W; const float* b; __half* Y; float scale;
    // Q pre-scaled by 1/sqrt(64)*log2(e): softmax in exp2 domain.
    if (blockIdx.z == 0)      { W = Wq; b = bq; Y = Qf;
                                scale = 0.125f * 1.44269504088896f; }
    else if (blockIdx.z == 1) { W = Wk; b = bk; Y = Kf; scale = 1.f; }
    else                      { W = Wv; b = bv; Y = Vf; scale = 1.f; }

    const int tid  = threadIdx.x;
    const int wid  = tid >> 5;
    const int lane = tid & 31;
    const int wm   = wid >> 1;
    const int wn   = wid & 1;
    const int m0 = blockIdx.y * 128, n0 = blockIdx.x * 128;
    const uint32_t sbase = smem_u32(smem);

    float acc[16][4];
#pragma unroll
    for (int i = 0; i < 16; i++)
#pragma unroll
        for (int j = 0; j < 4; j++) acc[i][j] = 0.f;

    const int la_row = lane & 15, la_kh = (lane >> 4) * 8;
    const int lb_j = lane & 7, lb_sel = lane >> 3;
    const int lb_rowoff = (lb_sel >> 1) * 8 + lb_j;
    const int lb_kh = (lb_sel & 1) * 8;

    mm_load_chunk(Xh, Xl, W, m0, n0, 0,  sbase,            tid);
    mm_load_chunk(Xh, Xl, W, m0, n0, 32, sbase + MM_STAGE, tid);

    for (int c = 0; c < DM / 32; c++) {       // 24 chunks
        if (c + 1 < DM / 32) { asm volatile("cp.async.wait_group 1;" ::: "memory"); }
        else                 { asm volatile("cp.async.wait_group 0;" ::: "memory"); }
        __syncthreads();
        const uint32_t stage = sbase + (uint32_t)(c % 3) * MM_STAGE;

#pragma unroll
        for (int ks = 0; ks < 2; ks++) {
            const int k16 = ks * 16;
            uint32_t ah[2][4], al[2][4];
#pragma unroll
            for (int im = 0; im < 2; im++) {
                uint32_t ra = (uint32_t)((wm * 32 + im * 16 + la_row) * MM_ROWB
                                         + (k16 + la_kh) * 2);
                ldsm4(ah[im], stage + ra);
                ldsm4(al[im], stage + MM_ARR + ra);
            }
#pragma unroll
            for (int bp = 0; bp < 4; bp++) {
                uint32_t rb = (uint32_t)((wn * 64 + bp * 16 + lb_rowoff) * MM_ROWB
                                         + (k16 + lb_kh) * 2);
                uint32_t bh[4];
                ldsm4(bh, stage + 2 * MM_ARR + rb);
#pragma unroll
                for (int im = 0; im < 2; im++)
#pragma unroll
                    for (int fp = 0; fp < 2; fp++) {
                        float* cc = acc[im * 8 + bp * 2 + fp];
                        mma16816h(cc, ah[im], bh[fp*2], bh[fp*2+1]);
                        mma16816h(cc, al[im], bh[fp*2], bh[fp*2+1]);
                    }
            }
        }

        if (c + 2 < DM / 32)
            mm_load_chunk(Xh, Xl, W, m0, n0, (c + 2) * 32,
                          sbase + (uint32_t)((c + 2) % 3) * MM_STAGE, tid);
    }

    const int rquad = lane >> 2, cpair = (lane & 3) * 2;
#pragma unroll
    for (int im = 0; im < 2; im++)
#pragma unroll
        for (int bp = 0; bp < 4; bp++)
#pragma unroll
            for (int fp = 0; fp < 2; fp++) {
                const float* cc = acc[im * 8 + bp * 2 + fp];
                int m = m0 + wm * 32 + im * 16 + rquad;
                int n = n0 + wn * 64 + bp * 16 + fp * 8 + cpair;
                float b0 = b[n], b1 = b[n + 1];
                float e0 = (cc[0] + b0) * scale, e1 = (cc[1] + b1) * scale;
                float e2 = (cc[2] + b0) * scale, e3 = (cc[3] + b1) * scale;
                *(uint32_t*)&Y[(size_t)m * DM + n]       = pack_h2(e0, e1);
                *(uint32_t*)&Y[(size_t)(m + 8) * DM + n] = pack_h2(e2, e3);
            }
}

// ----------------------------------------------------------------------------
// out GEMM: 128x64 tiles, 4-stage cp.async ring (R17). grid (12,32)=384 CTAs.
// ----------------------------------------------------------------------------
#define MO_BARR   5120                   // 64 rows x 80B
#define MO_STAGE  (2*MM_ARR + MO_BARR)   // 25600
#define MO_SMEM   (4*MO_STAGE)           // 102400 -> 2 CTAs/SM

__device__ __forceinline__ void mo_load_chunk(
    const __half* __restrict__ Ah, const __half* __restrict__ Al,
    const __half* __restrict__ B,
    int m0, int n0, int k0, uint32_t stage, int tid)
{
#pragma unroll
    for (int a = 0; a < 2; a++) {
        const __half* src = a ? Al : Ah;
#pragma unroll
        for (int i = 0; i < 2; i++) {
            int f = tid + i * 256;
            int r = f >> 2;
            int c8 = (f & 3) * 8;
            cp16(stage + a * MM_ARR + r * MM_ROWB + c8 * 2,
                 src + (size_t)(m0 + r) * DM + k0 + c8);
        }
    }
    {
        int r = tid >> 2;
        int c8 = (tid & 3) * 8;
        cp16(stage + 2 * MM_ARR + r * MM_ROWB + c8 * 2,
             B + (size_t)(n0 + r) * DM + k0 + c8);
    }
    asm volatile("cp.async.commit_group;" ::: "memory");
}

__global__ void __launch_bounds__(256, 2) tc_out_kernel(
    const __half* __restrict__ Ah, const __half* __restrict__ Al,
    const __half* __restrict__ W,
    const float* __restrict__ bias, float* __restrict__ Y)
{
    extern __shared__ char smem[];
    const int tid  = threadIdx.x;
    const int wid  = tid >> 5;
    const int lane = tid & 31;
    const int wm   = wid >> 1;
    const int wn   = wid & 1;
    const int m0 = blockIdx.y * 128, n0 = blockIdx.x * 64;
    const uint32_t sbase = smem_u32(smem);

    float acc[8][4];
#pragma unroll
    for (int i = 0; i < 8; i++)
#pragma unroll
        for (int j = 0; j < 4; j++) acc[i][j] = 0.f;

    const int la_row = lane & 15, la_kh = (lane >> 4) * 8;
    const int lb_j = lane & 7, lb_sel = lane >> 3;
    const int lb_rowoff = (lb_sel >> 1) * 8 + lb_j;
    const int lb_kh = (lb_sel & 1) * 8;

    // prologue: stages 0,1,2 (prefetch distance 3)
    mo_load_chunk(Ah, Al, W, m0, n0, 0,  sbase,                tid);
    mo_load_chunk(Ah, Al, W, m0, n0, 32, sbase +     MO_STAGE, tid);
    mo_load_chunk(Ah, Al, W, m0, n0, 64, sbase + 2 * MO_STAGE, tid);

    for (int c = 0; c < DM / 32; c++) {       // 24 chunks
        // stage c complete; up to 2 (stages c+1, c+2) may remain in flight
        if (c + 2 < DM / 32)      { asm volatile("cp.async.wait_group 2;" ::: "memory"); }
        else if (c + 1 < DM / 32) { asm volatile("cp.async.wait_group 1;" ::: "memory"); }
        else                      { asm volatile("cp.async.wait_group 0;" ::: "memory"); }
        __syncthreads();
        const uint32_t stage = sbase + (uint32_t)(c & 3) * MO_STAGE;

#pragma unroll
        for (int ks = 0; ks < 2; ks++) {
            const int k16 = ks * 16;
            uint32_t ah[2][4], al[2][4];
#pragma unroll
            for (int im = 0; im < 2; im++) {
                uint32_t ra = (uint32_t)((wm * 32 + im * 16 + la_row) * MM_ROWB
                                         + (k16 + la_kh) * 2);
                ldsm4(ah[im], stage + ra);
                ldsm4(al[im], stage + MM_ARR + ra);
            }
#pragma unroll
            for (int bp = 0; bp < 2; bp++) {
                uint32_t rb = (uint32_t)((wn * 32 + bp * 16 + lb_rowoff) * MM_ROWB
                                         + (k16 + lb_kh) * 2);
                uint32_t bh[4];
                ldsm4(bh, stage + 2 * MM_ARR + rb);
#pragma unroll
                for (int im = 0; im < 2; im++)
#pragma unroll
                    for (int fp = 0; fp < 2; fp++) {
                        float* cc = acc[im * 4 + bp * 2 + fp];
                        mma16816h(cc, ah[im], bh[fp*2], bh[fp*2+1]);
                        mma16816h(cc, al[im], bh[fp*2], bh[fp*2+1]);
                    }
            }
        }

        // load stage c+3 into ring slot (c+3)&3 = (c-1)&3 — freed: all warps
        // passed this iteration's sync, so none still reads stage c-1.
        if (c + 3 < DM / 32)
            mo_load_chunk(Ah, Al, W, m0, n0, (c + 3) * 32,
                          sbase + (uint32_t)((c + 3) & 3) * MO_STAGE, tid);
    }

    const int rquad = lane >> 2, cpair = (lane & 3) * 2;
#pragma unroll
    for (int im = 0; im < 2; im++)
#pragma unroll
        for (int bp = 0; bp < 2; bp++)
#pragma unroll
            for (int fp = 0; fp < 2; fp++) {
                const float* cc = acc[im * 4 + bp * 2 + fp];
                int m = m0 + wm * 32 + im * 16 + rquad;
                int n = n0 + wn * 32 + bp * 16 + fp * 8 + cpair;
                float b0 = bias[n], b1 = bias[n + 1];
                float2 o0 = make_float2(cc[0] + b0, cc[1] + b1);
                float2 o1 = make_float2(cc[2] + b0, cc[3] + b1);
                *(float2*)&Y[(size_t)m * DM + n]       = o0;
                *(float2*)&Y[(size_t)(m + 8) * DM + n] = o1;
            }
}

// ----------------------------------------------------------------------------
// fp16 flash attention, half2 static-max softmax (unchanged from R13/R16).
// ----------------------------------------------------------------------------
#define AT_ROWB 144
#define AT_QARR (128*AT_ROWB)            // 18432
#define AT_KARR (64*AT_ROWB)             // 9216
#define AT_STG  (2*AT_KARR)              // 18432 (K|V)
#define AT_SMEM (AT_QARR + 3*AT_STG)     // 73728 -> 2 CTAs/SM

__device__ __forceinline__ void at_load_kv16(
    const __half* __restrict__ K, const __half* __restrict__ V,
    uint32_t stg, int tok0, int h, int tid)
{
#pragma unroll
    for (int i = 0; i < 2; i++) {
        int f = tid + i * 256;        // 64 rows x 8 granules
        int r = f >> 3, c = f & 7;
        const size_t off = (size_t)(tok0 + r) * DM + h * DKH + c * 8;
        cp16(stg + r * AT_ROWB + c * 16,           K + off);
        cp16(stg + AT_KARR + r * AT_ROWB + c * 16, V + off);
    }
}

__global__ void __launch_bounds__(256, 2) attn_mma_kernel(
    const __half* __restrict__ Qf, const __half* __restrict__ Kf,
    const __half* __restrict__ Vf,
    __half* __restrict__ Ch, __half* __restrict__ Cl)
{
    extern __shared__ char smem[];
    const uint32_t sb = smem_u32(smem);
    const int tid = threadIdx.x, wid = tid >> 5, lane = tid & 31;
    const int b = blockIdx.z, h = blockIdx.y, q0 = blockIdx.x * 128;
    const int tokQ = b * SEQ + q0, tokK = b * SEQ;

    const int la_row = lane & 15, la_k = (lane >> 4) * 8;
    const int lb_j = lane & 7, lb_sel = lane >> 3;
    const int lb_row = (lb_sel >> 1) * 8 + lb_j;
    const int lb_k = (lb_sel & 1) * 8;

    const uint32_t st0 = sb + AT_QARR;
    uint32_t stg_of[3] = {st0, st0 + AT_STG, st0 + 2 * AT_STG};

    // ---- prologue: Q + stage0 (group), stage1 (group)
#pragma unroll
    for (int i = 0; i < 4; i++) {
        int f = tid + i * 256;        // 128 rows x 8 granules
        int r = f >> 3, c = f & 7;
        cp16(sb + r * AT_ROWB + c * 16,
             Qf + (size_t)(tokQ + r) * DM + h * DKH + c * 8);
    }
    at_load_kv16(Kf, Vf, stg_of[0], tokK, h, tid);
    asm volatile("cp.async.commit_group;" ::: "memory");
    at_load_kv16(Kf, Vf, stg_of[1], tokK + 64, h, tid);
    asm volatile("cp.async.commit_group;" ::: "memory");
    asm volatile("cp.async.wait_group 1;" ::: "memory");   // Q + s0 done
    __syncthreads();

    // Q fragments held in registers
    uint32_t qf[4][4];
#pragma unroll
    for (int kc = 0; kc < 4; kc++)
        ldsm4(qf[kc], sb + (uint32_t)((wid * 16 + la_row) * AT_ROWB
                                      + (kc * 16 + la_k) * 2));

    float of[8][4];
#pragma unroll
    for (int i = 0; i < 8; i++)
#pragma unroll
        for (int j = 0; j < 4; j++) of[i][j] = 0.f;
    float rs0 = 0.f, rs1 = 0.f;      // per-lane partial row sums (fp32)

#pragma unroll 1
    for (int t = 0; t < 32; t++) {
        if (t + 1 < 32) { asm volatile("cp.async.wait_group 1;" ::: "memory"); }
        else            { asm volatile("cp.async.wait_group 0;" ::: "memory"); }
        __syncthreads();            // stage t visible; all reads of t-1 done
        const uint32_t s = stg_of[t % 3];
        const uint32_t sv = s + AT_KARR;

        // ---- S = Q K^T : 16 rows x 64 keys
        float sf[8][4];
#pragma unroll
        for (int i = 0; i < 8; i++)
#pragma unroll
            for (int j = 0; j < 4; j++) sf[i][j] = 0.f;
#pragma unroll
        for (int kc = 0; kc < 4; kc++)
#pragma unroll
            for (int kn = 0; kn < 4; kn++) {
                uint32_t bh4[4];
                ldsm4(bh4, s + (uint32_t)((kn * 16 + lb_row) * AT_ROWB
                                          + (kc * 16 + lb_k) * 2));
                mma16816h(sf[2*kn],     qf[kc], bh4[0], bh4[1]);
                mma16816h(sf[2*kn + 1], qf[kc], bh4[2], bh4[3]);
            }

        // ---- softmax in half2: pack s -> f16x2 ex2 -> P frags + HADD2 sums
        uint32_t ph[4][4];
        uint32_t acc0 = 0u, acc1 = 0u;   // half2 (+0,+0)
#pragma unroll
        for (int kc = 0; kc < 4; kc++) {
            ph[kc][0] = h2ex2(pack_h2(sf[2*kc][0],   sf[2*kc][1]));
            ph[kc][1] = h2ex2(pack_h2(sf[2*kc][2],   sf[2*kc][3]));
            ph[kc][2] = h2ex2(pack_h2(sf[2*kc+1][0], sf[2*kc+1][1]));
            ph[kc][3] = h2ex2(pack_h2(sf[2*kc+1][2], sf[2*kc+1][3]));
            acc0 = hadd2(acc0, ph[kc][0]);
            acc0 = hadd2(acc0, ph[kc][2]);
            acc1 = hadd2(acc1, ph[kc][1]);
            acc1 = hadd2(acc1, ph[kc][3]);
        }
        {   // promote per-tile sums to fp32
            __half2 a0 = *(__half2*)&acc0, a1 = *(__half2*)&acc1;
            float2 f0 = __half22float2(a0), f1 = __half22float2(a1);
            rs0 += f0.x + f0.y;
            rs1 += f1.x + f1.y;
        }

        // ---- O += P V (V frags differ per (kc,dn): 16 trans-ldsm per tile)
#pragma unroll
        for (int kc = 0; kc < 4; kc++)
#pragma unroll
            for (int dn = 0; dn < 4; dn++) {
                uint32_t vh4[4];
                ldsm4t(vh4, sv + (uint32_t)((kc * 16 + la_row) * AT_ROWB
                                            + (dn * 16 + la_k) * 2));
                mma16816h(of[2*dn],     ph[kc], vh4[0], vh4[1]);
                mma16816h(of[2*dn + 1], ph[kc], vh4[2], vh4[3]);
            }

        // ---- prefetch stage t+2 (after compute: no warp still reads t-1)
        if (t + 2 < 32) {
            at_load_kv16(Kf, Vf, stg_of[(t + 2) % 3], tokK + (t + 2) * 64, h, tid);
            asm volatile("cp.async.commit_group;" ::: "memory");
        }
    }

    // ---- final row-sum reduction (4 lanes per row)
    rs0 += __shfl_xor_sync(0xffffffffu, rs0, 1);
    rs0 += __shfl_xor_sync(0xffffffffu, rs0, 2);
    rs1 += __shfl_xor_sync(0xffffffffu, rs1, 1);
    rs1 += __shfl_xor_sync(0xffffffffu, rs1, 2);
    const float i0 = 1.f / rs0, i1 = 1.f / rs1;

    // ---- epilogue: O/l -> ctx fp16 hi/lo
    const int rquad = lane >> 2, cpair = (lane & 3) * 2;
    const int tok = tokQ + wid * 16 + rquad;
#pragma unroll
    for (int j = 0; j < 8; j++) {
        int col = h * DKH + j * 8 + cpair;
        float e0 = of[j][0] * i0, e1 = of[j][1] * i0;
        float e2 = of[j][2] * i1, e3 = of[j][3] * i1;
        uint32_t h0 = pack_h2(e0, e1), h1 = pack_h2(e2, e3);
        *(uint32_t*)&Ch[(size_t)tok * DM + col]       = h0;
        *(uint32_t*)&Cl[(size_t)tok * DM + col]       = pack_h2lo(e0, e1, h0);
        *(uint32_t*)&Ch[(size_t)(tok + 8) * DM + col] = h1;
        *(uint32_t*)&Cl[(size_t)(tok + 8) * DM + col] = pack_h2lo(e2, e3, h1);
    }
}

// ----------------------------------------------------------------------------
// Launch
// ----------------------------------------------------------------------------
extern "C" void kernel_launch(void* const* d_in, const int* in_sizes, int n_in,
                              void* d_out, int out_size)
{
    (void)in_sizes; (void)n_in; (void)out_size;
    const float* x   = (const float*)d_in[0];
    const float* w_q = (const float*)d_in[1];
    const float* b_q = (const float*)d_in[2];
    const float* w_k = (const float*)d_in[3];
    const float* b_k = (const float*)d_in[4];
    const float* w_v = (const float*)d_in[5];
    const float* b_v = (const float*)d_in[6];
    const float* w_o = (const float*)d_in[7];
    const float* b_o = (const float*)d_in[8];
    float* out = (float*)d_out;

    __half *xh, *xl, *qf, *kf, *vf, *ch, *cl, *wq, *wk, *wv, *wo;
    cudaGetSymbolAddress((void**)&xh, g_xh); cudaGetSymbolAddress((void**)&xl, g_xl);
    cudaGetSymbolAddress((void**)&qf, g_qf);
    cudaGetSymbolAddress((void**)&kf, g_kf);
    cudaGetSymbolAddress((void**)&vf, g_vf);
    cudaGetSymbolAddress((void**)&ch, g_ch); cudaGetSymbolAddress((void**)&cl, g_cl);
    cudaGetSymbolAddress((void**)&wq, g_wq); cudaGetSymbolAddress((void**)&wk, g_wk);
    cudaGetSymbolAddress((void**)&wv, g_wv); cudaGetSymbolAddress((void**)&wo, g_wo);

    const int NTOT = NX4C + 4 * NW4C;
    cvt_all_kernel<<<(NTOT + 255) / 256, 256>>>(
        x, xh, xl, w_q, wq, w_k, wk, w_v, wv, w_o, wo);

    cudaFuncSetAttribute(tc_qkv_kernel,
                         cudaFuncAttributeMaxDynamicSharedMemorySize, MM_SMEM);
    cudaFuncSetAttribute(tc_out_kernel,
                         cudaFuncAttributeMaxDynamicSharedMemorySize, MO_SMEM);
    cudaFuncSetAttribute(attn_mma_kernel,
                         cudaFuncAttributeMaxDynamicSharedMemorySize, AT_SMEM);

    dim3 gqkv(DM / 128, MTOK / 128, 3);
    tc_qkv_kernel<<<gqkv, 256, MM_SMEM>>>(
        xh, xl, wq, b_q, qf, wk, b_k, kf, wv, b_v, vf);

    attn_mma_kernel<<<dim3(SEQ / 128, NH, BATCH), 256, AT_SMEM>>>(
        qf, kf, vf, ch, cl);

    dim3 go(DM / 64, MTOK / 128);        // (12, 32) = 384 CTAs
    tc_out_kernel<<<go, 256, MO_SMEM>>>(ch, cl, wo, b_o, out);
}